// round 1
// baseline (speedup 1.0000x reference)
#include <cuda_runtime.h>

// YOLO v1 loss, S=7, B=2, C=20.
// One thread per grid cell. obj==0 fast path reads only 3 scalars per cell.
// Argmax over the 2 boxes done via cross-multiplication (1 division total).
// wh sqrt term rewritten as a+b-2*sqrt(a*b) (2 sqrts instead of 4).

#define LAMBDA_COORD 5.0f
#define LAMBDA_NOOBJ 0.5f

__global__ __launch_bounds__(256)
void yolo_loss_kernel(const float* __restrict__ preds,
                      const float* __restrict__ labels,
                      float* __restrict__ out,
                      int ncells, float inv_bs)
{
    const float INV_S = 1.0f / 7.0f;
    int n = blockIdx.x * blockDim.x + threadIdx.x;
    float acc = 0.0f;

    if (n < ncells) {
        const float* p = preds  + (size_t)n * 30;
        const float* l = labels + (size_t)n * 30;

        float obj = __ldg(l + 4);   // exactly 0.0f or 1.0f by construction

        if (obj == 0.0f) {
            // loss = 0.5 * (pc0^2 + pc1^2); nothing else contributes.
            float pc0 = __ldg(p + 4);
            float pc1 = __ldg(p + 9);
            acc = LAMBDA_NOOBJ * (pc0 * pc0 + pc1 * pc1);
        } else {
            int within = n % 49;
            float gx = (float)(within % 7);
            float gy = (float)(within / 7);

            // preds channels 0..9 via five aligned float2 loads
            float2 p01 = *(const float2*)(p + 0);
            float2 p23 = *(const float2*)(p + 2);
            float2 p45 = *(const float2*)(p + 4);
            float2 p67 = *(const float2*)(p + 6);
            float2 p89 = *(const float2*)(p + 8);
            float px0 = p01.x, py0 = p01.y, pw0 = p23.x, ph0 = p23.y, pc0 = p45.x;
            float px1 = p45.y, py1 = p67.x, pw1 = p67.y, ph1 = p89.x, pc1 = p89.y;

            // label box
            float2 l01 = *(const float2*)(l + 0);
            float2 l23 = *(const float2*)(l + 2);
            float lx = l01.x, ly = l01.y, lw = l23.x, lh = l23.y;

            float l_cx = (gx + lx) * INV_S, l_cy = (gy + ly) * INV_S;
            float lminx = l_cx - lw * 0.5f, lmaxx = l_cx + lw * 0.5f;
            float lminy = l_cy - lh * 0.5f, lmaxy = l_cy + lh * 0.5f;
            float area_l = lw * lh;

            // box 0 IoU pieces
            float cx0 = (gx + px0) * INV_S, cy0 = (gy + py0) * INV_S;
            float iw0 = fminf(cx0 + pw0 * 0.5f, lmaxx) - fmaxf(cx0 - pw0 * 0.5f, lminx);
            float ih0 = fminf(cy0 + ph0 * 0.5f, lmaxy) - fmaxf(cy0 - ph0 * 0.5f, lminy);
            float inter0 = fmaxf(iw0, 0.0f) * fmaxf(ih0, 0.0f);
            float den0 = pw0 * ph0 + area_l - inter0 + 1e-10f;

            // box 1 IoU pieces
            float cx1 = (gx + px1) * INV_S, cy1 = (gy + py1) * INV_S;
            float iw1 = fminf(cx1 + pw1 * 0.5f, lmaxx) - fmaxf(cx1 - pw1 * 0.5f, lminx);
            float ih1 = fminf(cy1 + ph1 * 0.5f, lmaxy) - fmaxf(cy1 - ph1 * 0.5f, lminy);
            float inter1 = fmaxf(iw1, 0.0f) * fmaxf(ih1, 0.0f);
            float den1 = pw1 * ph1 + area_l - inter1 + 1e-10f;

            // argmax(iou) with first-wins tie-break (strict >), dens > 0
            bool sel1 = (inter1 * den0) > (inter0 * den1);

            float interR = sel1 ? inter1 : inter0;
            float denR   = sel1 ? den1   : den0;
            float iouR   = __fdividef(interR, denR);

            float pxr = sel1 ? px1 : px0;
            float pyr = sel1 ? py1 : py0;
            float pwr = sel1 ? pw1 : pw0;
            float phr = sel1 ? ph1 : ph0;
            float pcr = sel1 ? pc1 : pc0;
            float pco = sel1 ? pc0 : pc1;

            float dx = pxr - lx, dy = pyr - ly;
            // (sqrt(a)-sqrt(b))^2 = a + b - 2*sqrt(a*b)
            float wh_err = (pwr + lw - 2.0f * sqrtf(pwr * lw))
                         + (phr + lh - 2.0f * sqrtf(phr * lh));
            float dconf = pcr - iouR;

            acc = LAMBDA_COORD * (dx * dx + dy * dy + wh_err)
                + dconf * dconf
                + LAMBDA_NOOBJ * (pco * pco);

            // class term: channels 10..29
            #pragma unroll
            for (int k = 0; k < 10; k++) {
                float2 pp = *(const float2*)(p + 10 + 2 * k);
                float2 ll = *(const float2*)(l + 10 + 2 * k);
                float d0 = pp.x - ll.x;
                float d1 = pp.y - ll.y;
                acc += d0 * d0 + d1 * d1;
            }
        }
    }

    // block reduction
    #pragma unroll
    for (int o = 16; o > 0; o >>= 1)
        acc += __shfl_down_sync(0xffffffffu, acc, o);

    __shared__ float wsum[8];
    int lane = threadIdx.x & 31;
    int wid  = threadIdx.x >> 5;
    if (lane == 0) wsum[wid] = acc;
    __syncthreads();

    if (threadIdx.x < 8) {
        float v = wsum[threadIdx.x];
        #pragma unroll
        for (int o = 4; o > 0; o >>= 1)
            v += __shfl_down_sync(0x000000ffu, v, o);
        if (threadIdx.x == 0)
            atomicAdd(out, v * inv_bs);
    }
}

extern "C" void kernel_launch(void* const* d_in, const int* in_sizes, int n_in,
                              void* d_out, int out_size)
{
    const float* preds  = (const float*)d_in[0];
    const float* labels = (const float*)d_in[1];
    float* out = (float*)d_out;

    int ncells = in_sizes[0] / 30;          // bs * 7 * 7
    int bs     = ncells / 49;
    float inv_bs = 1.0f / (float)bs;

    cudaMemsetAsync(out, 0, (size_t)out_size * sizeof(float));

    int block = 256;
    int grid = (ncells + block - 1) / block;
    yolo_loss_kernel<<<grid, block>>>(preds, labels, out, ncells, inv_bs);
}